// round 12
// baseline (speedup 1.0000x reference)
#include <cuda_runtime.h>
#include <cuda_fp16.h>
#include <stdint.h>

#define NB   2
#define SEQ  2048
#define DM   1024
#define NH   16
#define DKH  64

// ===================== device scratch (no allocations) =====================
// A-operands (x inputs + ctx) tiled: [mblk(256r)][kchunk(64)] 32KB swizzled blocks
// W tiled: [nblk(128r)][kchunk(64)] 16KB swizzled blocks
__device__ __align__(128) __half g_xq[(size_t)NB*SEQ*DM];
__device__ __align__(128) __half g_xk[(size_t)NB*SEQ*DM];
__device__ __align__(128) __half g_xv[(size_t)NB*SEQ*DM];
__device__ __align__(128) __half g_wq[(size_t)DM*DM];
__device__ __align__(128) __half g_wk[(size_t)DM*DM];
__device__ __align__(128) __half g_wv[(size_t)DM*DM];
__device__ __align__(128) __half g_wo[(size_t)DM*DM];
// Q tiled: [n][h][qblk(256r x 64d)] 32KB blocks; K: [n][h][kblk(64r x 64d)] 8KB; vT: [n][h][kblk(64d x 64s)] 8KB
__device__ __align__(128) __half g_q[(size_t)NB*NH*SEQ*DKH];    // pre-scaled by 0.125*log2(e)
__device__ __align__(128) __half g_k[(size_t)NB*NH*SEQ*DKH];
__device__ __align__(128) __half g_vT[(size_t)NB*NH*DKH*SEQ];
__device__ __align__(128) __half g_ctx[(size_t)NB*SEQ*DM];      // A-tiled for O-proj
__device__ uint32_t g_mbits[(size_t)NB*SEQ*64];   // [n][q][kv/32], bit=1 -> masked

// ===================== helpers =====================
__device__ __forceinline__ uint32_t smem_u32(const void* p) {
    uint32_t a;
    asm("{ .reg .u64 t; cvta.to.shared.u64 t, %1; cvt.u32.u64 %0, t; }" : "=r"(a) : "l"(p));
    return a;
}
__device__ __forceinline__ void ldsm4(uint32_t* r, uint32_t a) {
    asm volatile("ldmatrix.sync.aligned.m8n8.x4.shared.b16 {%0,%1,%2,%3}, [%4];"
        : "=r"(r[0]), "=r"(r[1]), "=r"(r[2]), "=r"(r[3]) : "r"(a));
}
__device__ __forceinline__ void mma_fp16(float* d, const uint32_t* a, uint32_t b0, uint32_t b1) {
    asm volatile(
        "mma.sync.aligned.m16n8k16.row.col.f32.f16.f16.f32 "
        "{%0,%1,%2,%3}, {%4,%5,%6,%7}, {%8,%9}, {%0,%1,%2,%3};"
        : "+f"(d[0]), "+f"(d[1]), "+f"(d[2]), "+f"(d[3])
        : "r"(a[0]), "r"(a[1]), "r"(a[2]), "r"(a[3]), "r"(b0), "r"(b1));
}
__device__ __forceinline__ uint32_t cvt2h(float h, float l) {
    uint32_t d;
    asm("cvt.rn.f16x2.f32 %0, %1, %2;" : "=r"(d) : "f"(h), "f"(l));
    return d;
}
__device__ __forceinline__ uint32_t ex2h2(uint32_t x) {
    uint32_t d;
    asm("ex2.approx.f16x2 %0, %1;" : "=r"(d) : "r"(x));
    return d;
}
__device__ __forceinline__ uint32_t zmask2(uint32_t w, int sh) {
    uint32_t t = w >> sh;
    return (t & 1u) * 0x0000FFFFu + (t & 2u) * 0x7FFF8000u;
}

// bulk async copy global -> shared::cta with mbarrier completion
#define BULK_G2S(dst, src, bytes, mbar) \
    asm volatile("cp.async.bulk.shared::cta.global.mbarrier::complete_tx::bytes [%0], [%1], %2, [%3];" \
        :: "r"((uint32_t)(dst)), "l"(src), "r"((uint32_t)(bytes)), "r"((uint32_t)(mbar)) : "memory")
#define MBAR_INIT(mb, c)   asm volatile("mbarrier.init.shared.b64 [%0], %1;" :: "r"(mb), "r"((uint32_t)(c)) : "memory")
#define MBAR_EXPECT(mb, n) asm volatile("mbarrier.arrive.expect_tx.shared.b64 _, [%0], %1;" :: "r"(mb), "r"((uint32_t)(n)) : "memory")
#define MBAR_WAIT(mbar_addr, ph) do { \
    uint32_t _mb = (uint32_t)(mbar_addr); uint32_t _p = (uint32_t)(ph); uint32_t _done; \
    asm volatile("{\n\t.reg .pred p;\n\tmbarrier.try_wait.parity.acquire.cta.shared::cta.b64 p, [%1], %2;\n\tselp.b32 %0, 1, 0, p;\n\t}" \
        : "=r"(_done) : "r"(_mb), "r"(_p) : "memory"); \
    if (!_done) { \
        asm volatile("{\n\t.reg .pred P1;\n\tWL_%=:\n\tmbarrier.try_wait.parity.acquire.cta.shared::cta.b64 P1, [%0], %1, 0x989680;\n\t@P1 bra.uni WD_%=;\n\tbra.uni WL_%=;\n\tWD_%=:\n\t}" \
            :: "r"(_mb), "r"(_p) : "memory"); \
    } } while (0)

// swizzle within a 128B-row tile: 16B chunk ch of row r
#define ASWZ(r, ch) ((uint32_t)(((r) << 7) + ((((ch) ^ ((r) & 7))) << 4)))

__device__ __forceinline__ uint32_t pack2h(float a, float b) {
    __half2 h = __floats2half2_rn(a, b);
    return *(uint32_t*)&h;
}
#define ONES_H2 0x3C003C00u   // half2 (1.0, 1.0)

// ===================== prep: convert + tile-swizzle =====================
// inputs (A-layout): [mblk][kchunk] 32KB blocks ; weights: [nblk][kchunk] 16KB blocks
__global__ void cvt_all_kernel(
    const float* __restrict__ q,  const float* __restrict__ k,  const float* __restrict__ v,
    const float* __restrict__ Wq, const float* __restrict__ Wk, const float* __restrict__ Wv,
    const float* __restrict__ Wo)
{
    const int INPC = NB * SEQ * DM / 8;   // 524288 16B-chunks per input
    const int WC   = DM * DM / 8;         // 131072 per weight
    int gid = blockIdx.x * blockDim.x + threadIdx.x;
    const float* src;
    char* dstb;
    int e;
    bool isA;
    if (gid < 3 * INPC) {
        int seg = gid / INPC;
        e = gid - seg * INPC;
        src = (seg == 0) ? q : (seg == 1) ? k : v;
        dstb = (char*)((seg == 0) ? g_xq : (seg == 1) ? g_xk : g_xv);
        isA = true;
    } else {
        int r2 = gid - 3 * INPC;
        int seg = r2 / WC;
        if (seg >= 4) return;
        e = r2 - seg * WC;
        src = (seg == 0) ? Wq : (seg == 1) ? Wk : (seg == 2) ? Wv : Wo;
        dstb = (char*)((seg == 0) ? g_wq : (seg == 1) ? g_wk : (seg == 2) ? g_wv : g_wo);
        isA = false;
    }
    int row = e >> 7;            // 128 chunks per 1024-col row
    int ch8 = e & 127;           // chunk in row
    int kchunk = ch8 >> 3, ch = ch8 & 7;
    size_t off;
    if (isA) off = ((size_t)((row >> 8) * 16 + kchunk) << 15) + ASWZ(row & 255, ch);
    else     off = ((size_t)((row >> 7) * 16 + kchunk) << 14) + ASWZ(row & 127, ch);
    const float* s = src + (size_t)row * DM + ch8 * 8;
    float4 x0 = *(const float4*)s;
    float4 x1 = *(const float4*)(s + 4);
    uint4 o;
    o.x = pack2h(x0.x, x0.y);
    o.y = pack2h(x0.z, x0.w);
    o.z = pack2h(x1.x, x1.y);
    o.w = pack2h(x1.z, x1.w);
    *(uint4*)(dstb + off) = o;
}

__global__ void maskpack_kernel(const int* __restrict__ mask)
{
    int w = blockIdx.x * blockDim.x + threadIdx.x;
    if (w >= NB * SEQ * 64) return;
    const int* p = mask + (size_t)w * 32;
    uint32_t bits = 0;
#pragma unroll
    for (int j = 0; j < 32; j += 4) {
        int4 m4 = *(const int4*)(p + j);
        bits |= (m4.x ? 1u : 0u) << j       | (m4.y ? 1u : 0u) << (j + 1)
              | (m4.z ? 1u : 0u) << (j + 2) | (m4.w ? 1u : 0u) << (j + 3);
    }
    g_mbits[w] = bits;
}

// ===================== projection GEMM: tile 256x128, warp 64x64, bulk loads =====================
// smem: 2 stages x (A 32KB + W 16KB) = 96KB; mbar full[2]
#define PROJ_SMEM (2 * 49152 + 16)

template<int MODE>   // 0: Q/K tiled out, 1: fp32 out, 2: vT tiled out
__global__ void __launch_bounds__(256, 1) proj_kernel(
    const __half* __restrict__ A, const __half* __restrict__ W,
    const float* __restrict__ bias, void* out, float scale)
{
    extern __shared__ __align__(128) char smem[];
    uint32_t sb = smem_u32(smem);
    int tid = threadIdx.x, lane = tid & 31, warp = tid >> 5;
    int mblk = blockIdx.y;               // 256-row block
    int nblk = blockIdx.x;               // 128-col block
    int bm = mblk * 256, bn = nblk * 128;
    uint32_t mb0 = sb + 2 * 49152, mb1 = mb0 + 8;

    if (tid == 0) { MBAR_INIT(mb0, 1); MBAR_INIT(mb1, 1); }
    __syncthreads();
    if (tid == 0) {
        MBAR_EXPECT(mb0, 49152);
        BULK_G2S(sb,         (const char*)A + ((size_t)(mblk * 16 + 0) << 15), 32768, mb0);
        BULK_G2S(sb + 32768, (const char*)W + ((size_t)(nblk * 16 + 0) << 14), 16384, mb0);
    }

    int wm = (warp >> 1) * 64;
    int wn = (warp & 1) * 64;
    int a_r = (lane & 7) + ((lane >> 3) & 1) * 8;
    int a_c = lane >> 4;
    int b_r = (lane & 7) + (lane >> 4) * 8;
    int b_c = (lane >> 3) & 1;

    float acc[4][8][4];
#pragma unroll
    for (int i = 0; i < 4; i++)
#pragma unroll
        for (int j = 0; j < 8; j++)
#pragma unroll
            for (int t = 0; t < 4; t++) acc[i][j][t] = 0.0f;

    for (int c = 0; c < 16; c++) {
        MBAR_WAIT((c & 1) ? mb1 : mb0, (c >> 1) & 1);
        __syncthreads();
        if (c + 1 < 16 && tid == 0) {
            uint32_t st = sb + ((c + 1) & 1) * 49152;
            uint32_t mbx = ((c + 1) & 1) ? mb1 : mb0;
            MBAR_EXPECT(mbx, 49152);
            BULK_G2S(st,         (const char*)A + ((size_t)(mblk * 16 + c + 1) << 15), 32768, mbx);
            BULK_G2S(st + 32768, (const char*)W + ((size_t)(nblk * 16 + c + 1) << 14), 16384, mbx);
        }
        uint32_t ab = sb + (c & 1) * 49152;
        uint32_t wb = ab + 32768;
#pragma unroll
        for (int k16 = 0; k16 < 4; k16++) {
            uint32_t bh[4][4];
#pragma unroll
            for (int ngp = 0; ngp < 4; ngp++)
                ldsm4(bh[ngp], wb + ASWZ(wn + ngp * 16 + b_r, k16 * 2 + b_c));
#pragma unroll
            for (int mt = 0; mt < 4; mt++) {
                uint32_t ah[4];
                ldsm4(ah, ab + ASWZ(wm + mt * 16 + a_r, k16 * 2 + a_c));
#pragma unroll
                for (int ngp = 0; ngp < 4; ngp++) {
                    mma_fp16(acc[mt][2 * ngp],     ah, bh[ngp][0], bh[ngp][1]);
                    mma_fp16(acc[mt][2 * ngp + 1], ah, bh[ngp][2], bh[ngp][3]);
                }
            }
        }
    }

    // epilogue
    int lr = lane >> 2, lc = (lane & 3) * 2;
#pragma unroll
    for (int mt = 0; mt < 4; mt++) {
#pragma unroll
        for (int i = 0; i < 2; i++) {
            int m = bm + wm + mt * 16 + lr + i * 8;
            int n2 = m >> 11, qq = m & (SEQ - 1);
#pragma unroll
            for (int n8 = 0; n8 < 8; n8++) {
                int o = bn + wn + n8 * 8 + lc;
                float v0 = (acc[mt][n8][2 * i + 0] + __ldg(bias + o))     * scale;
                float v1 = (acc[mt][n8][2 * i + 1] + __ldg(bias + o + 1)) * scale;
                if (MODE == 1) {
                    *(float2*)((float*)out + (size_t)m * DM + o) = make_float2(v0, v1);
                } else {
                    int hh = o >> 6, dd = o & 63;
                    if (MODE == 0) {
                        // Q: 256-row 32KB tiles ; K: 64-row 8KB tiles (selected by scale!=1 trick? no: out ptr distinct)
                        // Q and K share MODE 0 but tile size differs -> use DKH block by SEQ block size:
                        // we store Q-style only when out==g_q; pass tile kind via scale? cleaner: MODE0=Q, MODE3=K
                        size_t off = ((size_t)((n2 * NH + hh) * 8 + (qq >> 8)) << 15)
                                   + ASWZ(qq & 255, dd >> 3) + (dd & 7) * 2;
                        *(uint32_t*)((char*)out + off) = pack2h(v0, v1);
                    } else {   // MODE 2: vT tiles [dk][seq64]
                        size_t off = ((size_t)((n2 * NH + hh) * 32 + (qq >> 6)) << 13);
                        uint32_t c1 = ASWZ(dd,     (qq >> 3) & 7) + (qq & 7) * 2;
                        uint32_t c2 = ASWZ(dd + 1, (qq >> 3) & 7) + (qq & 7) * 2;
                        *(__half*)((char*)out + off + c1) = __float2half_rn(v0);
                        *(__half*)((char*)out + off + c2) = __float2half_rn(v1);
                    }
                }
            }
        }
    }
}

// K projection epilogue variant (64-row 8KB tiles)
__global__ void __launch_bounds__(256, 1) projk_kernel(
    const __half* __restrict__ A, const __half* __restrict__ W,
    const float* __restrict__ bias, void* out)
{
    extern __shared__ __align__(128) char smem[];
    uint32_t sb = smem_u32(smem);
    int tid = threadIdx.x, lane = tid & 31, warp = tid >> 5;
    int mblk = blockIdx.y, nblk = blockIdx.x;
    int bm = mblk * 256, bn = nblk * 128;
    uint32_t mb0 = sb + 2 * 49152, mb1 = mb0 + 8;

    if (tid == 0) { MBAR_INIT(mb0, 1); MBAR_INIT(mb1, 1); }
    __syncthreads();
    if (tid == 0) {
        MBAR_EXPECT(mb0, 49152);
        BULK_G2S(sb,         (const char*)A + ((size_t)(mblk * 16) << 15), 32768, mb0);
        BULK_G2S(sb + 32768, (const char*)W + ((size_t)(nblk * 16) << 14), 16384, mb0);
    }
    int wm = (warp >> 1) * 64, wn = (warp & 1) * 64;
    int a_r = (lane & 7) + ((lane >> 3) & 1) * 8;
    int a_c = lane >> 4;
    int b_r = (lane & 7) + (lane >> 4) * 8;
    int b_c = (lane >> 3) & 1;

    float acc[4][8][4];
#pragma unroll
    for (int i = 0; i < 4; i++)
#pragma unroll
        for (int j = 0; j < 8; j++)
#pragma unroll
            for (int t = 0; t < 4; t++) acc[i][j][t] = 0.0f;

    for (int c = 0; c < 16; c++) {
        MBAR_WAIT((c & 1) ? mb1 : mb0, (c >> 1) & 1);
        __syncthreads();
        if (c + 1 < 16 && tid == 0) {
            uint32_t st = sb + ((c + 1) & 1) * 49152;
            uint32_t mbx = ((c + 1) & 1) ? mb1 : mb0;
            MBAR_EXPECT(mbx, 49152);
            BULK_G2S(st,         (const char*)A + ((size_t)(mblk * 16 + c + 1) << 15), 32768, mbx);
            BULK_G2S(st + 32768, (const char*)W + ((size_t)(nblk * 16 + c + 1) << 14), 16384, mbx);
        }
        uint32_t ab = sb + (c & 1) * 49152;
        uint32_t wb = ab + 32768;
#pragma unroll
        for (int k16 = 0; k16 < 4; k16++) {
            uint32_t bh[4][4];
#pragma unroll
            for (int ngp = 0; ngp < 4; ngp++)
                ldsm4(bh[ngp], wb + ASWZ(wn + ngp * 16 + b_r, k16 * 2 + b_c));
#pragma unroll
            for (int mt = 0; mt < 4; mt++) {
                uint32_t ah[4];
                ldsm4(ah, ab + ASWZ(wm + mt * 16 + a_r, k16 * 2 + a_c));
#pragma unroll
                for (int ngp = 0; ngp < 4; ngp++) {
                    mma_fp16(acc[mt][2 * ngp],     ah, bh[ngp][0], bh[ngp][1]);
                    mma_fp16(acc[mt][2 * ngp + 1], ah, bh[ngp][2], bh[ngp][3]);
                }
            }
        }
    }
    int lr = lane >> 2, lc = (lane & 3) * 2;
#pragma unroll
    for (int mt = 0; mt < 4; mt++) {
#pragma unroll
        for (int i = 0; i < 2; i++) {
            int m = bm + wm + mt * 16 + lr + i * 8;
            int n2 = m >> 11, qq = m & (SEQ - 1);
#pragma unroll
            for (int n8 = 0; n8 < 8; n8++) {
                int o = bn + wn + n8 * 8 + lc;
                float v0 = acc[mt][n8][2 * i + 0] + __ldg(bias + o);
                float v1 = acc[mt][n8][2 * i + 1] + __ldg(bias + o + 1);
                int hh = o >> 6, dd = o & 63;
                size_t off = ((size_t)((n2 * NH + hh) * 32 + (qq >> 6)) << 13)
                           + ASWZ(qq & 63, dd >> 3) + (dd & 7) * 2;
                *(uint32_t*)((char*)out + off) = pack2h(v0, v1);
            }
        }
    }
}

// ===================== attention: 256 q-rows/CTA, bulk KV ring =====================
// smem: Q 32KB @0 ; KV ring 3 x 16KB @32768 (K +0, V +8192) ; mbars @81920
#define ATT_SMEM (32768 + 3 * 16384 + 48)

__global__ void __launch_bounds__(256, 1) attn_kernel()
{
    extern __shared__ __align__(128) char smem[];
    uint32_t sb = smem_u32(smem);
    int tid = threadIdx.x, lane = tid & 31, warp = tid >> 5;   // warp 0..7, 32 rows each
    int qb = blockIdx.x, h = blockIdx.y, n = blockIdx.z;
    uint32_t qmb = sb + 81920;
    uint32_t fmb[3] = { sb + 81928, sb + 81936, sb + 81944 };

    const char* qsrc = (const char*)g_q  + ((size_t)((n * NH + h) * 8 + qb) << 15);
    const char* ksrc = (const char*)g_k  + ((size_t)((n * NH + h) * 32) << 13);
    const char* vsrc = (const char*)g_vT + ((size_t)((n * NH + h) * 32) << 13);
    const uint32_t* mbase = g_mbits + (size_t)n * SEQ * 64;

    if (tid == 0) {
        MBAR_INIT(qmb, 1);
        MBAR_INIT(fmb[0], 1); MBAR_INIT(fmb[1], 1); MBAR_INIT(fmb[2], 1);
    }
    __syncthreads();
    if (tid == 0) {
        MBAR_EXPECT(qmb, 32768);
        BULK_G2S(sb, qsrc, 32768, qmb);
#pragma unroll
        for (int p = 0; p < 2; p++) {
            MBAR_EXPECT(fmb[p], 16384);
            BULK_G2S(sb + 32768 + p * 16384,        ksrc + (size_t)p * 8192, 8192, fmb[p]);
            BULK_G2S(sb + 32768 + p * 16384 + 8192, vsrc + (size_t)p * 8192, 8192, fmb[p]);
        }
    }

    int a_r = (lane & 7) + ((lane >> 3) & 1) * 8;
    int a_c = lane >> 4;
    int b_r = (lane & 7) + (lane >> 4) * 8;
    int b_c = (lane >> 3) & 1;
    int lr = lane >> 2, lc = (lane & 3) * 2;
    int q0 = qb * 256 + warp * 32 + lr;

    uint32_t qa[4][2][4];
    float oacc[2][8][4];
    float lacc[2][4];
#pragma unroll
    for (int mi = 0; mi < 2; mi++) {
#pragma unroll
        for (int ng = 0; ng < 8; ng++)
#pragma unroll
            for (int t = 0; t < 4; t++) oacc[mi][ng][t] = 0.0f;
#pragma unroll
        for (int t = 0; t < 4; t++) lacc[mi][t] = 0.0f;
    }

    for (int kt = 0; kt < 32; kt++) {
        int st = kt % 3;
        MBAR_WAIT(fmb[st], (kt / 3) & 1);
        __syncthreads();
        if (kt + 2 < 32 && tid == 0) {
            int s2 = (kt + 2) % 3;
            MBAR_EXPECT(fmb[s2], 16384);
            BULK_G2S(sb + 32768 + s2 * 16384,        ksrc + (size_t)(kt + 2) * 8192, 8192, fmb[s2]);
            BULK_G2S(sb + 32768 + s2 * 16384 + 8192, vsrc + (size_t)(kt + 2) * 8192, 8192, fmb[s2]);
        }
        if (kt == 0) {
            MBAR_WAIT(qmb, 0);
#pragma unroll
            for (int k16 = 0; k16 < 4; k16++)
#pragma unroll
                for (int mi = 0; mi < 2; mi++)
                    ldsm4(qa[k16][mi], sb + ASWZ(warp * 32 + mi * 16 + a_r, k16 * 2 + a_c));
        }
        uint2 mw[2][2];
#pragma unroll
        for (int mi = 0; mi < 2; mi++)
#pragma unroll
            for (int ri = 0; ri < 2; ri++)
                mw[mi][ri] = *(const uint2*)(mbase + (size_t)(q0 + mi * 16 + ri * 8) * 64 + 2 * kt);

        uint32_t kvb = sb + 32768 + st * 16384;

        float sacc[2][8][4];
#pragma unroll
        for (int mi = 0; mi < 2; mi++)
#pragma unroll
            for (int ng = 0; ng < 8; ng++)
#pragma unroll
                for (int t = 0; t < 4; t++) sacc[mi][ng][t] = 0.0f;

#pragma unroll
        for (int k16 = 0; k16 < 4; k16++) {
#pragma unroll
            for (int ngp = 0; ngp < 4; ngp++) {
                uint32_t bh[4];
                ldsm4(bh, kvb + ASWZ(ngp * 16 + b_r, k16 * 2 + b_c));
                mma_fp16(sacc[0][2 * ngp],     qa[k16][0], bh[0], bh[1]);
                mma_fp16(sacc[0][2 * ngp + 1], qa[k16][0], bh[2], bh[3]);
                mma_fp16(sacc[1][2 * ngp],     qa[k16][1], bh[0], bh[1]);
                mma_fp16(sacc[1][2 * ngp + 1], qa[k16][1], bh[2], bh[3]);
            }
        }

#pragma unroll
        for (int g = 0; g < 4; g++) {
            uint32_t pa[2][4];
#pragma unroll
            for (int mi = 0; mi < 2; mi++) {
                uint32_t w0 = (g < 2) ? mw[mi][0].x : mw[mi][0].y;
                uint32_t w1 = (g < 2) ? mw[mi][1].x : mw[mi][1].y;
                int sh = ((g & 1) << 4) + lc;
                const float* s0 = sacc[mi][2 * g];
                const float* s1 = sacc[mi][2 * g + 1];
                pa[mi][0] = ex2h2(cvt2h(s0[1], s0[0])) & ~zmask2(w0, sh);
                pa[mi][1] = ex2h2(cvt2h(s0[3], s0[2])) & ~zmask2(w1, sh);
                pa[mi][2] = ex2h2(cvt2h(s1[1], s1[0])) & ~zmask2(w0, sh + 8);
                pa[mi][3] = ex2h2(cvt2h(s1[3], s1[2])) & ~zmask2(w1, sh + 8);
                mma_fp16(lacc[mi], pa[mi], ONES_H2, ONES_H2);
            }
#pragma unroll
            for (int ngd = 0; ngd < 4; ngd++) {
                uint32_t bh[4];
                ldsm4(bh, kvb + 8192 + ASWZ(ngd * 16 + b_r, g * 2 + b_c));
                mma_fp16(oacc[0][2 * ngd],     pa[0], bh[0], bh[1]);
                mma_fp16(oacc[0][2 * ngd + 1], pa[0], bh[2], bh[3]);
                mma_fp16(oacc[1][2 * ngd],     pa[1], bh[0], bh[1]);
                mma_fp16(oacc[1][2 * ngd + 1], pa[1], bh[2], bh[3]);
            }
        }
    }

    // epilogue -> ctx in A-tiled layout: mblk = n*8 + qb, kchunk = h
    char* cbase = (char*)g_ctx + ((size_t)((n * 8 + qb) * 16 + h) << 15);
#pragma unroll
    for (int mi = 0; mi < 2; mi++) {
        float i0 = 1.0f / lacc[mi][0];
        float i1 = 1.0f / lacc[mi][2];
        int r = warp * 32 + mi * 16 + lr;
#pragma unroll
        for (int ng = 0; ng < 8; ng++) {
            *(uint32_t*)(cbase + ASWZ(r,     ng) + lc * 2) = pack2h(oacc[mi][ng][0] * i0, oacc[mi][ng][1] * i0);
            *(uint32_t*)(cbase + ASWZ(r + 8, ng) + lc * 2) = pack2h(oacc[mi][ng][2] * i1, oacc[mi][ng][3] * i1);
        }
    }
}

// ===================== launch =====================
extern "C" void kernel_launch(void* const* d_in, const int* in_sizes, int n_in,
                              void* d_out, int out_size)
{
    const float* q   = (const float*)d_in[0];
    const float* k   = (const float*)d_in[1];
    const float* v   = (const float*)d_in[2];
    const int*   msk = (const int*)d_in[3];
    const float* Wq  = (const float*)d_in[4];
    const float* bq  = (const float*)d_in[5];
    const float* Wk  = (const float*)d_in[6];
    const float* bk  = (const float*)d_in[7];
    const float* Wv  = (const float*)d_in[8];
    const float* bv  = (const float*)d_in[9];
    const float* Wo  = (const float*)d_in[10];
    const float* bo  = (const float*)d_in[11];
    float* out = (float*)d_out;

    __half *xq, *xk, *xv, *wq, *wk, *wv, *wo, *qp, *kp, *vt, *cx;
    cudaGetSymbolAddress((void**)&xq, g_xq);
    cudaGetSymbolAddress((void**)&xk, g_xk);
    cudaGetSymbolAddress((void**)&xv, g_xv);
    cudaGetSymbolAddress((void**)&wq, g_wq);
    cudaGetSymbolAddress((void**)&wk, g_wk);
    cudaGetSymbolAddress((void**)&wv, g_wv);
    cudaGetSymbolAddress((void**)&wo, g_wo);
    cudaGetSymbolAddress((void**)&qp, g_q);
    cudaGetSymbolAddress((void**)&kp, g_k);
    cudaGetSymbolAddress((void**)&vt, g_vT);
    cudaGetSymbolAddress((void**)&cx, g_ctx);

    cudaFuncSetAttribute(proj_kernel<0>, cudaFuncAttributeMaxDynamicSharedMemorySize, PROJ_SMEM);
    cudaFuncSetAttribute(proj_kernel<1>, cudaFuncAttributeMaxDynamicSharedMemorySize, PROJ_SMEM);
    cudaFuncSetAttribute(proj_kernel<2>, cudaFuncAttributeMaxDynamicSharedMemorySize, PROJ_SMEM);
    cudaFuncSetAttribute(projk_kernel,   cudaFuncAttributeMaxDynamicSharedMemorySize, PROJ_SMEM);
    cudaFuncSetAttribute(attn_kernel,    cudaFuncAttributeMaxDynamicSharedMemorySize, ATT_SMEM);

    const int TOTC = 3 * (NB * SEQ * DM / 8) + 4 * (DM * DM / 8);   // 2097152
    cvt_all_kernel<<<TOTC / 256, 256>>>(q, k, v, Wq, Wk, Wv, Wo);
    maskpack_kernel<<<NB * SEQ * 64 / 256, 256>>>(msk);

    dim3 pgrid(DM / 128, NB * SEQ / 256);
    proj_kernel<0><<<pgrid, 256, PROJ_SMEM>>>(xq, wq, bq, qp, 0.18033688011112043f);  // Q (pre-scaled)
    projk_kernel  <<<pgrid, 256, PROJ_SMEM>>>(xk, wk, bk, kp);                        // K
    proj_kernel<2><<<pgrid, 256, PROJ_SMEM>>>(xv, wv, bv, vt, 1.0f);                  // V (transposed tiles)

    attn_kernel<<<dim3(SEQ / 256, NH, NB), 256, ATT_SMEM>>>();

    proj_kernel<1><<<pgrid, 256, PROJ_SMEM>>>(cx, wo, bo, out, 1.0f);                 // O
}